// round 4
// baseline (speedup 1.0000x reference)
#include <cuda_runtime.h>
#include <math.h>
#include <string.h>

// Problem constants
#define N_B    4
#define S_LEN  1024
#define E_DIM  768
#define H_HEADS 12
constexpr int NS  = N_B * S_LEN;       // 4096 rows
constexpr int HE  = H_HEADS * E_DIM;   // 9216
constexpr int FF  = 4 * E_DIM;         // 3072

typedef unsigned long long u64;

// ---------------- scratch (allocation-free: __device__ globals) ----------------
__device__ float g_x    [NS * E_DIM];
__device__ float g_q    [H_HEADS * NS * E_DIM];
__device__ float g_k    [H_HEADS * NS * E_DIM];
__device__ float g_v    [H_HEADS * NS * E_DIM];
__device__ float g_sc   [(long)H_HEADS * N_B * S_LEN * S_LEN];
__device__ float g_heads[H_HEADS * NS * E_DIM];
__device__ float g_cat  [NS * HE];
__device__ float g_mha  [NS * E_DIM];
__device__ float g_y2   [NS * E_DIM];
__device__ float g_hbuf [NS * FF];

// ---------------- f32x2 packed math ----------------
__device__ __forceinline__ u64 dup2(float a) {
    u64 r;
    asm("mov.b64 %0, {%1, %1};" : "=l"(r) : "f"(a));
    return r;
}
__device__ __forceinline__ void fma2(u64& c, u64 a, u64 b) {
    asm("fma.rn.f32x2 %0, %1, %2, %0;" : "+l"(c) : "l"(a), "l"(b));
}

// ---------------- reductions ----------------
__device__ __forceinline__ float warpReduceSum(float v) {
    #pragma unroll
    for (int o = 16; o > 0; o >>= 1) v += __shfl_xor_sync(0xffffffffu, v, o);
    return v;
}
__device__ __forceinline__ float warpReduceMax(float v) {
    #pragma unroll
    for (int o = 16; o > 0; o >>= 1) v = fmaxf(v, __shfl_xor_sync(0xffffffffu, v, o));
    return v;
}

// ---------------- LayerNorm (optionally fused residual add) ----------------
__global__ void ln_kernel(const float* __restrict__ in, const float* __restrict__ resid,
                          const float* __restrict__ gamma, const float* __restrict__ beta,
                          float* __restrict__ out) {
    long base = (long)blockIdx.x * E_DIM;
    int tid = threadIdx.x;
    float vals[3];
    float s = 0.f, s2 = 0.f;
    #pragma unroll
    for (int i = 0; i < 3; i++) {
        int c = tid + i * 256;
        float v = in[base + c];
        if (resid) v += resid[base + c];
        vals[i] = v; s += v; s2 += v * v;
    }
    __shared__ float shs[8], shs2[8];
    s = warpReduceSum(s); s2 = warpReduceSum(s2);
    int lane = tid & 31, w = tid >> 5;
    if (lane == 0) { shs[w] = s; shs2[w] = s2; }
    __syncthreads();
    if (tid < 32) {
        float a = (lane < 8) ? shs[lane]  : 0.f;
        float b = (lane < 8) ? shs2[lane] : 0.f;
        a = warpReduceSum(a); b = warpReduceSum(b);
        if (lane == 0) { shs[0] = a; shs2[0] = b; }
    }
    __syncthreads();
    float mean = shs[0] * (1.f / E_DIM);
    float var  = shs2[0] * (1.f / E_DIM) - mean * mean;
    float rstd = rsqrtf(var + 1e-5f);
    #pragma unroll
    for (int i = 0; i < 3; i++) {
        int c = tid + i * 256;
        out[base + c] = (vals[i] - mean) * rstd * gamma[c] + beta[c];
    }
}

// ---------------- causal softmax (writes zeros in masked region) ----------------
__global__ void softmax_causal(float* __restrict__ scores) {
    int srow = blockIdx.x;
    float* row = scores + ((long)blockIdx.y * S_LEN + srow) * S_LEN;
    int tid = threadIdx.x;
    const float scale = 0.03608439182435161f;  // 1/sqrt(768)
    float v[4];
    float mx = -1e30f;
    #pragma unroll
    for (int i = 0; i < 4; i++) {
        int t = tid + i * 256;
        float val = (t <= srow) ? row[t] * scale : -1e30f;
        v[i] = val; mx = fmaxf(mx, val);
    }
    __shared__ float sh[8];
    int lane = tid & 31, w = tid >> 5;
    mx = warpReduceMax(mx);
    if (lane == 0) sh[w] = mx;
    __syncthreads();
    if (tid < 32) {
        float m2 = (lane < 8) ? sh[lane] : -1e30f;
        m2 = warpReduceMax(m2);
        if (lane == 0) sh[0] = m2;
    }
    __syncthreads();
    mx = sh[0];
    __syncthreads();
    float sum = 0.f;
    #pragma unroll
    for (int i = 0; i < 4; i++) {
        int t = tid + i * 256;
        float e = (t <= srow) ? __expf(v[i] - mx) : 0.f;
        v[i] = e; sum += e;
    }
    sum = warpReduceSum(sum);
    if (lane == 0) sh[w] = sum;
    __syncthreads();
    if (tid < 32) {
        float s2 = (lane < 8) ? sh[lane] : 0.f;
        s2 = warpReduceSum(s2);
        if (lane == 0) sh[0] = s2;
    }
    __syncthreads();
    float inv = 1.f / sh[0];
    #pragma unroll
    for (int i = 0; i < 4; i++) {
        int t = tid + i * 256;
        row[t] = v[i] * inv;   // exact zeros where masked
    }
}

// ---------------- heads [h][n*s][e] -> cat [n*s][h*768+e] ----------------
__global__ void heads_to_cat_kernel(const float4* __restrict__ heads4,
                                    float4* __restrict__ cat4) {
    int idx = blockIdx.x * 256 + threadIdx.x;
    const int HE4 = HE / 4;
    const int E4  = E_DIM / 4;
    int row = idx / HE4;
    int c4  = idx % HE4;
    int h   = c4 / E4;
    int e4  = c4 % E4;
    int n    = row >> 10;
    int sidx = row & 1023;
    long src = (((long)(h * N_B + n) * S_LEN + sidx) * E4 + e4);
    cat4[idx] = heads4[src];
}

// ---------------- SGEMM with packed f32x2 FMA ----------------
// TRANSB=false: B is [K,N] ldb=N;  TRANSB=true: B is [N,K] ldb=K (C=A@B^T)
// epi: 0 = bias only, 1 = bias+exact GELU, 2 = bias + residual(res, ldc)
// causal: 0 none; 1 skip blocks col0 > row0+BM-1 (scores QK^T);
//         2 limit K loop to row0+BM (attn@V; A upper-tri is exact zeros)
// Requires M%128==0, N%128==0, K%16==0. lda == K.
template<bool TRANSB>
__global__ void __launch_bounds__(256, 1)
sgemm_kernel(const float* __restrict__ A, const float* __restrict__ B,
             const float* __restrict__ bias, const float* __restrict__ res,
             float* __restrict__ C,
             int M, int N, int K, int ldb, int ldc,
             long strideA, long strideB, long strideBias, long strideC,
             int epi, int causal) {
    constexpr int BM = 128, BN = 128, BK = 16;
    __shared__ float As[BK][BM];
    __shared__ float Bs[BK][BN];

    int row0 = blockIdx.y * BM;
    int col0 = blockIdx.x * BN;
    if (causal == 1 && col0 > row0 + BM - 1) return;   // fully-masked block

    int Keff = K;
    if (causal == 2) { int kl = row0 + BM; Keff = kl < K ? kl : K; }

    int z = blockIdx.z;
    A += strideA * z;
    B += strideB * z;
    C += strideC * z;
    if (bias) bias += strideBias * z;

    int tid = threadIdx.x;
    int tx = tid & 15, ty = tid >> 4;

    u64 acc2[8][4];
    #pragma unroll
    for (int i = 0; i < 8; i++)
        #pragma unroll
        for (int j = 0; j < 4; j++) acc2[i][j] = 0ULL;

    // register prefetch buffers
    float4 pa[2], pb[2];

    // indices for loads (constant across iterations)
    const int a_mm0  = (tid)       >> 2;
    const int a_kk0  = ((tid) & 3) * 4;
    const int a_mm1  = (tid + 256) >> 2;
    const int a_kk1  = ((tid + 256) & 3) * 4;

    auto loadA = [&](int k0) {
        pa[0] = *reinterpret_cast<const float4*>(&A[(long)(row0 + a_mm0) * K + k0 + a_kk0]);
        pa[1] = *reinterpret_cast<const float4*>(&A[(long)(row0 + a_mm1) * K + k0 + a_kk1]);
    };
    auto loadB = [&](int k0) {
        if (!TRANSB) {
            #pragma unroll
            for (int l = 0; l < 2; l++) {
                int j = tid + l * 256;
                int kk = j >> 5;
                int nn = (j & 31) * 4;
                pb[l] = *reinterpret_cast<const float4*>(&B[(long)(k0 + kk) * ldb + col0 + nn]);
            }
        } else {
            #pragma unroll
            for (int l = 0; l < 2; l++) {
                int j = tid + l * 256;
                int nn  = j >> 2;
                int kk4 = (j & 3) * 4;
                pb[l] = *reinterpret_cast<const float4*>(&B[(long)(col0 + nn) * ldb + k0 + kk4]);
            }
        }
    };
    auto stash = [&]() {
        As[a_kk0 + 0][a_mm0] = pa[0].x; As[a_kk0 + 1][a_mm0] = pa[0].y;
        As[a_kk0 + 2][a_mm0] = pa[0].z; As[a_kk0 + 3][a_mm0] = pa[0].w;
        As[a_kk1 + 0][a_mm1] = pa[1].x; As[a_kk1 + 1][a_mm1] = pa[1].y;
        As[a_kk1 + 2][a_mm1] = pa[1].z; As[a_kk1 + 3][a_mm1] = pa[1].w;
        if (!TRANSB) {
            #pragma unroll
            for (int l = 0; l < 2; l++) {
                int j = tid + l * 256;
                int kk = j >> 5;
                int nn = (j & 31) * 4;
                *reinterpret_cast<float4*>(&Bs[kk][nn]) = pb[l];
            }
        } else {
            #pragma unroll
            for (int l = 0; l < 2; l++) {
                int j = tid + l * 256;
                int nn  = j >> 2;
                int kk4 = (j & 3) * 4;
                Bs[kk4 + 0][nn] = pb[l].x; Bs[kk4 + 1][nn] = pb[l].y;
                Bs[kk4 + 2][nn] = pb[l].z; Bs[kk4 + 3][nn] = pb[l].w;
            }
        }
    };

    loadA(0); loadB(0);
    for (int k0 = 0; k0 < Keff; k0 += BK) {
        stash();
        __syncthreads();
        bool more = (k0 + BK) < Keff;
        if (more) { loadA(k0 + BK); loadB(k0 + BK); }

        #pragma unroll
        for (int kk = 0; kk < BK; kk++) {
            float a[8];
            *reinterpret_cast<float4*>(&a[0]) = *reinterpret_cast<const float4*>(&As[kk][ty * 8]);
            *reinterpret_cast<float4*>(&a[4]) = *reinterpret_cast<const float4*>(&As[kk][ty * 8 + 4]);
            ulonglong2 bb0 = *reinterpret_cast<const ulonglong2*>(&Bs[kk][tx * 8]);
            ulonglong2 bb1 = *reinterpret_cast<const ulonglong2*>(&Bs[kk][tx * 8 + 4]);
            u64 b2[4] = {bb0.x, bb0.y, bb1.x, bb1.y};
            #pragma unroll
            for (int i = 0; i < 8; i++) {
                u64 ad = dup2(a[i]);
                #pragma unroll
                for (int j = 0; j < 4; j++) fma2(acc2[i][j], ad, b2[j]);
            }
        }
        __syncthreads();
    }

    int r = row0 + ty * 8;
    int c = col0 + tx * 8;
    float bv[8];
    #pragma unroll
    for (int j = 0; j < 8; j++) bv[j] = bias ? bias[c + j] : 0.f;
    #pragma unroll
    for (int i = 0; i < 8; i++) {
        float accf[8];
        memcpy(accf, acc2[i], 32);
        #pragma unroll
        for (int j = 0; j < 8; j++) {
            float v = accf[j] + bv[j];
            if (epi == 1)      v = v * normcdff(v);                   // exact GELU
            else if (epi == 2) v += res[(long)(r + i) * ldc + c + j]; // residual add
            C[(long)(r + i) * ldc + c + j] = v;
        }
    }
}

// ---------------- launch ----------------
extern "C" void kernel_launch(void* const* d_in, const int* in_sizes, int n_in,
                              void* d_out, int out_size) {
    const float* inputs = (const float*)d_in[0];
    const float* g1  = (const float*)d_in[1];
    const float* b1  = (const float*)d_in[2];
    const float* Wq  = (const float*)d_in[3];
    const float* bq  = (const float*)d_in[4];
    const float* Wk  = (const float*)d_in[5];
    const float* bk  = (const float*)d_in[6];
    const float* Wv  = (const float*)d_in[7];
    const float* bv  = (const float*)d_in[8];
    const float* Wc  = (const float*)d_in[9];
    const float* bc  = (const float*)d_in[10];
    const float* g2  = (const float*)d_in[11];
    const float* b2  = (const float*)d_in[12];
    const float* Wfc = (const float*)d_in[13];
    const float* bfc = (const float*)d_in[14];
    const float* Wp  = (const float*)d_in[15];
    const float* bp  = (const float*)d_in[16];
    float* out = (float*)d_out;

    float *x, *q, *k, *v, *sc, *hd, *cat, *mha, *y2, *hb;
    cudaGetSymbolAddress((void**)&x,   g_x);
    cudaGetSymbolAddress((void**)&q,   g_q);
    cudaGetSymbolAddress((void**)&k,   g_k);
    cudaGetSymbolAddress((void**)&v,   g_v);
    cudaGetSymbolAddress((void**)&sc,  g_sc);
    cudaGetSymbolAddress((void**)&hd,  g_heads);
    cudaGetSymbolAddress((void**)&cat, g_cat);
    cudaGetSymbolAddress((void**)&mha, g_mha);
    cudaGetSymbolAddress((void**)&y2,  g_y2);
    cudaGetSymbolAddress((void**)&hb,  g_hbuf);

    const long QKV_STRIDE = (long)NS * E_DIM;
    const long ATT_A      = (long)S_LEN * E_DIM;
    const long SC_STRIDE  = (long)S_LEN * S_LEN;

    // 1) LN1
    ln_kernel<<<NS, 256>>>(inputs, nullptr, g1, b1, x);

    // 2) Q,K,V projections
    dim3 gQKV(E_DIM / 128, NS / 128, H_HEADS);
    sgemm_kernel<false><<<gQKV, 256>>>(x, Wq, bq, nullptr, q, NS, E_DIM, E_DIM,
                                       E_DIM, E_DIM, 0, (long)E_DIM * E_DIM, E_DIM, QKV_STRIDE, 0, 0);
    sgemm_kernel<false><<<gQKV, 256>>>(x, Wk, bk, nullptr, k, NS, E_DIM, E_DIM,
                                       E_DIM, E_DIM, 0, (long)E_DIM * E_DIM, E_DIM, QKV_STRIDE, 0, 0);
    sgemm_kernel<false><<<gQKV, 256>>>(x, Wv, bv, nullptr, v, NS, E_DIM, E_DIM,
                                       E_DIM, E_DIM, 0, (long)E_DIM * E_DIM, E_DIM, QKV_STRIDE, 0, 0);

    // 3) scores = Q @ K^T per (h,n), skipping fully-masked blocks
    dim3 gSC(S_LEN / 128, S_LEN / 128, H_HEADS * N_B);
    sgemm_kernel<true><<<gSC, 256>>>(q, k, nullptr, nullptr, sc, S_LEN, S_LEN, E_DIM,
                                     E_DIM, S_LEN, ATT_A, ATT_A, 0, SC_STRIDE, 0, 1);

    // 4) causal softmax (writes exact zeros in masked region)
    softmax_causal<<<dim3(S_LEN, H_HEADS * N_B), 256>>>(sc);

    // 5) heads = attn @ V, K-loop limited by causal structure
    dim3 gAV(E_DIM / 128, S_LEN / 128, H_HEADS * N_B);
    sgemm_kernel<false><<<gAV, 256>>>(sc, v, nullptr, nullptr, hd, S_LEN, E_DIM, S_LEN,
                                      E_DIM, E_DIM, SC_STRIDE, ATT_A, 0, ATT_A, 0, 2);

    // 6) transpose heads -> cat
    heads_to_cat_kernel<<<(NS * HE / 4) / 256, 256>>>((const float4*)hd, (float4*)cat);

    // 7) c_proj
    dim3 gCP(E_DIM / 128, NS / 128, 1);
    sgemm_kernel<false><<<gCP, 256>>>(cat, Wc, bc, nullptr, mha, NS, E_DIM, HE,
                                      E_DIM, E_DIM, 0, 0, 0, 0, 0, 0);

    // 8) y2 = LN2(mha + x)
    ln_kernel<<<NS, 256>>>(mha, x, g2, b2, y2);

    // 9) fc + GELU
    dim3 gFC(FF / 128, NS / 128, 1);
    sgemm_kernel<false><<<gFC, 256>>>(y2, Wfc, bfc, nullptr, hb, NS, FF, E_DIM,
                                      FF, FF, 0, 0, 0, 0, 1, 0);

    // 10) proj + residual -> out
    dim3 gPJ(E_DIM / 128, NS / 128, 1);
    sgemm_kernel<false><<<gPJ, 256>>>(hb, Wp, bp, y2, out, NS, E_DIM, FF,
                                      E_DIM, E_DIM, 0, 0, 0, 0, 2, 0);
}

// round 5
// speedup vs baseline: 1.0004x; 1.0004x over previous
#include <cuda_runtime.h>
#include <math.h>
#include <string.h>

// Problem constants
#define N_B    4
#define S_LEN  1024
#define E_DIM  768
#define H_HEADS 12
constexpr int NS  = N_B * S_LEN;       // 4096 rows
constexpr int HE  = H_HEADS * E_DIM;   // 9216
constexpr int FF  = 4 * E_DIM;         // 3072

typedef unsigned long long u64;

// ---------------- scratch (allocation-free: __device__ globals) ----------------
__device__ float g_x    [NS * E_DIM];
__device__ float g_q    [H_HEADS * NS * E_DIM];
__device__ float g_k    [H_HEADS * NS * E_DIM];
__device__ float g_v    [H_HEADS * NS * E_DIM];
__device__ float g_sc   [(long)H_HEADS * N_B * S_LEN * S_LEN];
__device__ float g_heads[H_HEADS * NS * E_DIM];
__device__ float g_cat  [NS * HE];
__device__ float g_mha  [NS * E_DIM];
__device__ float g_y2   [NS * E_DIM];
__device__ float g_hbuf [NS * FF];

// ---------------- f32x2 packed math ----------------
__device__ __forceinline__ u64 dup2(float a) {
    u64 r;
    asm("mov.b64 %0, {%1, %1};" : "=l"(r) : "f"(a));
    return r;
}
__device__ __forceinline__ void fma2(u64& c, u64 a, u64 b) {
    asm("fma.rn.f32x2 %0, %1, %2, %0;" : "+l"(c) : "l"(a), "l"(b));
}

// ---------------- reductions ----------------
__device__ __forceinline__ float warpReduceSum(float v) {
    #pragma unroll
    for (int o = 16; o > 0; o >>= 1) v += __shfl_xor_sync(0xffffffffu, v, o);
    return v;
}
__device__ __forceinline__ float warpReduceMax(float v) {
    #pragma unroll
    for (int o = 16; o > 0; o >>= 1) v = fmaxf(v, __shfl_xor_sync(0xffffffffu, v, o));
    return v;
}

// ---------------- LayerNorm (optionally fused residual add) ----------------
__global__ void ln_kernel(const float* __restrict__ in, const float* __restrict__ resid,
                          const float* __restrict__ gamma, const float* __restrict__ beta,
                          float* __restrict__ out) {
    long base = (long)blockIdx.x * E_DIM;
    int tid = threadIdx.x;
    float vals[3];
    float s = 0.f, s2 = 0.f;
    #pragma unroll
    for (int i = 0; i < 3; i++) {
        int c = tid + i * 256;
        float v = in[base + c];
        if (resid) v += resid[base + c];
        vals[i] = v; s += v; s2 += v * v;
    }
    __shared__ float shs[8], shs2[8];
    s = warpReduceSum(s); s2 = warpReduceSum(s2);
    int lane = tid & 31, w = tid >> 5;
    if (lane == 0) { shs[w] = s; shs2[w] = s2; }
    __syncthreads();
    if (tid < 32) {
        float a = (lane < 8) ? shs[lane]  : 0.f;
        float b = (lane < 8) ? shs2[lane] : 0.f;
        a = warpReduceSum(a); b = warpReduceSum(b);
        if (lane == 0) { shs[0] = a; shs2[0] = b; }
    }
    __syncthreads();
    float mean = shs[0] * (1.f / E_DIM);
    float var  = shs2[0] * (1.f / E_DIM) - mean * mean;
    float rstd = rsqrtf(var + 1e-5f);
    #pragma unroll
    for (int i = 0; i < 3; i++) {
        int c = tid + i * 256;
        out[base + c] = (vals[i] - mean) * rstd * gamma[c] + beta[c];
    }
}

// ---------------- causal softmax (writes zeros in masked region) ----------------
__global__ void softmax_causal(float* __restrict__ scores) {
    int srow = blockIdx.x;
    float* row = scores + ((long)blockIdx.y * S_LEN + srow) * S_LEN;
    int tid = threadIdx.x;
    const float scale = 0.03608439182435161f;  // 1/sqrt(768)
    float v[4];
    float mx = -1e30f;
    #pragma unroll
    for (int i = 0; i < 4; i++) {
        int t = tid + i * 256;
        float val = (t <= srow) ? row[t] * scale : -1e30f;
        v[i] = val; mx = fmaxf(mx, val);
    }
    __shared__ float sh[8];
    int lane = tid & 31, w = tid >> 5;
    mx = warpReduceMax(mx);
    if (lane == 0) sh[w] = mx;
    __syncthreads();
    if (tid < 32) {
        float m2 = (lane < 8) ? sh[lane] : -1e30f;
        m2 = warpReduceMax(m2);
        if (lane == 0) sh[0] = m2;
    }
    __syncthreads();
    mx = sh[0];
    __syncthreads();
    float sum = 0.f;
    #pragma unroll
    for (int i = 0; i < 4; i++) {
        int t = tid + i * 256;
        float e = (t <= srow) ? __expf(v[i] - mx) : 0.f;
        v[i] = e; sum += e;
    }
    sum = warpReduceSum(sum);
    if (lane == 0) sh[w] = sum;
    __syncthreads();
    if (tid < 32) {
        float s2 = (lane < 8) ? sh[lane] : 0.f;
        s2 = warpReduceSum(s2);
        if (lane == 0) sh[0] = s2;
    }
    __syncthreads();
    float inv = 1.f / sh[0];
    #pragma unroll
    for (int i = 0; i < 4; i++) {
        int t = tid + i * 256;
        row[t] = v[i] * inv;   // exact zeros where masked
    }
}

// ---------------- heads [h][n*s][e] -> cat [n*s][h*768+e] ----------------
__global__ void heads_to_cat_kernel(const float4* __restrict__ heads4,
                                    float4* __restrict__ cat4) {
    int idx = blockIdx.x * 256 + threadIdx.x;
    const int HE4 = HE / 4;
    const int E4  = E_DIM / 4;
    int row = idx / HE4;
    int c4  = idx % HE4;
    int h   = c4 / E4;
    int e4  = c4 % E4;
    int n    = row >> 10;
    int sidx = row & 1023;
    long src = (((long)(h * N_B + n) * S_LEN + sidx) * E4 + e4);
    cat4[idx] = heads4[src];
}

// ---------------- SGEMM with packed f32x2 FMA ----------------
// TRANSB=false: B is [K,N] ldb=N;  TRANSB=true: B is [N,K] ldb=K (C=A@B^T)
// epi: 0 = bias only, 1 = bias+exact GELU, 2 = bias + residual(res, ldc)
// causal: 0 none; 1 skip blocks col0 > row0+BM-1 (scores QK^T);
//         2 limit K loop to row0+BM (attn@V; A upper-tri is exact zeros)
// Requires M%128==0, N%128==0, K%16==0. lda == K.
template<bool TRANSB>
__global__ void __launch_bounds__(256, 1)
sgemm_kernel(const float* __restrict__ A, const float* __restrict__ B,
             const float* __restrict__ bias, const float* __restrict__ res,
             float* __restrict__ C,
             int M, int N, int K, int ldb, int ldc,
             long strideA, long strideB, long strideBias, long strideC,
             int epi, int causal) {
    constexpr int BM = 128, BN = 128, BK = 16;
    __shared__ float As[BK][BM];
    __shared__ float Bs[BK][BN];

    int row0 = blockIdx.y * BM;
    int col0 = blockIdx.x * BN;
    if (causal == 1 && col0 > row0 + BM - 1) return;   // fully-masked block

    int Keff = K;
    if (causal == 2) { int kl = row0 + BM; Keff = kl < K ? kl : K; }

    int z = blockIdx.z;
    A += strideA * z;
    B += strideB * z;
    C += strideC * z;
    if (bias) bias += strideBias * z;

    int tid = threadIdx.x;
    int tx = tid & 15, ty = tid >> 4;

    u64 acc2[8][4];
    #pragma unroll
    for (int i = 0; i < 8; i++)
        #pragma unroll
        for (int j = 0; j < 4; j++) acc2[i][j] = 0ULL;

    // register prefetch buffers
    float4 pa[2], pb[2];

    // indices for loads (constant across iterations)
    const int a_mm0  = (tid)       >> 2;
    const int a_kk0  = ((tid) & 3) * 4;
    const int a_mm1  = (tid + 256) >> 2;
    const int a_kk1  = ((tid + 256) & 3) * 4;

    auto loadA = [&](int k0) {
        pa[0] = *reinterpret_cast<const float4*>(&A[(long)(row0 + a_mm0) * K + k0 + a_kk0]);
        pa[1] = *reinterpret_cast<const float4*>(&A[(long)(row0 + a_mm1) * K + k0 + a_kk1]);
    };
    auto loadB = [&](int k0) {
        if (!TRANSB) {
            #pragma unroll
            for (int l = 0; l < 2; l++) {
                int j = tid + l * 256;
                int kk = j >> 5;
                int nn = (j & 31) * 4;
                pb[l] = *reinterpret_cast<const float4*>(&B[(long)(k0 + kk) * ldb + col0 + nn]);
            }
        } else {
            #pragma unroll
            for (int l = 0; l < 2; l++) {
                int j = tid + l * 256;
                int nn  = j >> 2;
                int kk4 = (j & 3) * 4;
                pb[l] = *reinterpret_cast<const float4*>(&B[(long)(col0 + nn) * ldb + k0 + kk4]);
            }
        }
    };
    auto stash = [&]() {
        As[a_kk0 + 0][a_mm0] = pa[0].x; As[a_kk0 + 1][a_mm0] = pa[0].y;
        As[a_kk0 + 2][a_mm0] = pa[0].z; As[a_kk0 + 3][a_mm0] = pa[0].w;
        As[a_kk1 + 0][a_mm1] = pa[1].x; As[a_kk1 + 1][a_mm1] = pa[1].y;
        As[a_kk1 + 2][a_mm1] = pa[1].z; As[a_kk1 + 3][a_mm1] = pa[1].w;
        if (!TRANSB) {
            #pragma unroll
            for (int l = 0; l < 2; l++) {
                int j = tid + l * 256;
                int kk = j >> 5;
                int nn = (j & 31) * 4;
                *reinterpret_cast<float4*>(&Bs[kk][nn]) = pb[l];
            }
        } else {
            #pragma unroll
            for (int l = 0; l < 2; l++) {
                int j = tid + l * 256;
                int nn  = j >> 2;
                int kk4 = (j & 3) * 4;
                Bs[kk4 + 0][nn] = pb[l].x; Bs[kk4 + 1][nn] = pb[l].y;
                Bs[kk4 + 2][nn] = pb[l].z; Bs[kk4 + 3][nn] = pb[l].w;
            }
        }
    };

    loadA(0); loadB(0);
    for (int k0 = 0; k0 < Keff; k0 += BK) {
        stash();
        __syncthreads();
        bool more = (k0 + BK) < Keff;
        if (more) { loadA(k0 + BK); loadB(k0 + BK); }

        #pragma unroll
        for (int kk = 0; kk < BK; kk++) {
            float a[8];
            *reinterpret_cast<float4*>(&a[0]) = *reinterpret_cast<const float4*>(&As[kk][ty * 8]);
            *reinterpret_cast<float4*>(&a[4]) = *reinterpret_cast<const float4*>(&As[kk][ty * 8 + 4]);
            ulonglong2 bb0 = *reinterpret_cast<const ulonglong2*>(&Bs[kk][tx * 8]);
            ulonglong2 bb1 = *reinterpret_cast<const ulonglong2*>(&Bs[kk][tx * 8 + 4]);
            u64 b2[4] = {bb0.x, bb0.y, bb1.x, bb1.y};
            #pragma unroll
            for (int i = 0; i < 8; i++) {
                u64 ad = dup2(a[i]);
                #pragma unroll
                for (int j = 0; j < 4; j++) fma2(acc2[i][j], ad, b2[j]);
            }
        }
        __syncthreads();
    }

    int r = row0 + ty * 8;
    int c = col0 + tx * 8;
    float bv[8];
    #pragma unroll
    for (int j = 0; j < 8; j++) bv[j] = bias ? bias[c + j] : 0.f;
    #pragma unroll
    for (int i = 0; i < 8; i++) {
        float accf[8];
        memcpy(accf, acc2[i], 32);
        #pragma unroll
        for (int j = 0; j < 8; j++) {
            float v = accf[j] + bv[j];
            if (epi == 1)      v = v * normcdff(v);                   // exact GELU
            else if (epi == 2) v += res[(long)(r + i) * ldc + c + j]; // residual add
            C[(long)(r + i) * ldc + c + j] = v;
        }
    }
}

// ---------------- launch ----------------
extern "C" void kernel_launch(void* const* d_in, const int* in_sizes, int n_in,
                              void* d_out, int out_size) {
    const float* inputs = (const float*)d_in[0];
    const float* g1  = (const float*)d_in[1];
    const float* b1  = (const float*)d_in[2];
    const float* Wq  = (const float*)d_in[3];
    const float* bq  = (const float*)d_in[4];
    const float* Wk  = (const float*)d_in[5];
    const float* bk  = (const float*)d_in[6];
    const float* Wv  = (const float*)d_in[7];
    const float* bv  = (const float*)d_in[8];
    const float* Wc  = (const float*)d_in[9];
    const float* bc  = (const float*)d_in[10];
    const float* g2  = (const float*)d_in[11];
    const float* b2  = (const float*)d_in[12];
    const float* Wfc = (const float*)d_in[13];
    const float* bfc = (const float*)d_in[14];
    const float* Wp  = (const float*)d_in[15];
    const float* bp  = (const float*)d_in[16];
    float* out = (float*)d_out;

    float *x, *q, *k, *v, *sc, *hd, *cat, *mha, *y2, *hb;
    cudaGetSymbolAddress((void**)&x,   g_x);
    cudaGetSymbolAddress((void**)&q,   g_q);
    cudaGetSymbolAddress((void**)&k,   g_k);
    cudaGetSymbolAddress((void**)&v,   g_v);
    cudaGetSymbolAddress((void**)&sc,  g_sc);
    cudaGetSymbolAddress((void**)&hd,  g_heads);
    cudaGetSymbolAddress((void**)&cat, g_cat);
    cudaGetSymbolAddress((void**)&mha, g_mha);
    cudaGetSymbolAddress((void**)&y2,  g_y2);
    cudaGetSymbolAddress((void**)&hb,  g_hbuf);

    const long QKV_STRIDE = (long)NS * E_DIM;
    const long ATT_A      = (long)S_LEN * E_DIM;
    const long SC_STRIDE  = (long)S_LEN * S_LEN;

    // 1) LN1
    ln_kernel<<<NS, 256>>>(inputs, nullptr, g1, b1, x);

    // 2) Q,K,V projections
    dim3 gQKV(E_DIM / 128, NS / 128, H_HEADS);
    sgemm_kernel<false><<<gQKV, 256>>>(x, Wq, bq, nullptr, q, NS, E_DIM, E_DIM,
                                       E_DIM, E_DIM, 0, (long)E_DIM * E_DIM, E_DIM, QKV_STRIDE, 0, 0);
    sgemm_kernel<false><<<gQKV, 256>>>(x, Wk, bk, nullptr, k, NS, E_DIM, E_DIM,
                                       E_DIM, E_DIM, 0, (long)E_DIM * E_DIM, E_DIM, QKV_STRIDE, 0, 0);
    sgemm_kernel<false><<<gQKV, 256>>>(x, Wv, bv, nullptr, v, NS, E_DIM, E_DIM,
                                       E_DIM, E_DIM, 0, (long)E_DIM * E_DIM, E_DIM, QKV_STRIDE, 0, 0);

    // 3) scores = Q @ K^T per (h,n), skipping fully-masked blocks
    dim3 gSC(S_LEN / 128, S_LEN / 128, H_HEADS * N_B);
    sgemm_kernel<true><<<gSC, 256>>>(q, k, nullptr, nullptr, sc, S_LEN, S_LEN, E_DIM,
                                     E_DIM, S_LEN, ATT_A, ATT_A, 0, SC_STRIDE, 0, 1);

    // 4) causal softmax (writes exact zeros in masked region)
    softmax_causal<<<dim3(S_LEN, H_HEADS * N_B), 256>>>(sc);

    // 5) heads = attn @ V, K-loop limited by causal structure
    dim3 gAV(E_DIM / 128, S_LEN / 128, H_HEADS * N_B);
    sgemm_kernel<false><<<gAV, 256>>>(sc, v, nullptr, nullptr, hd, S_LEN, E_DIM, S_LEN,
                                      E_DIM, E_DIM, SC_STRIDE, ATT_A, 0, ATT_A, 0, 2);

    // 6) transpose heads -> cat
    heads_to_cat_kernel<<<(NS * HE / 4) / 256, 256>>>((const float4*)hd, (float4*)cat);

    // 7) c_proj
    dim3 gCP(E_DIM / 128, NS / 128, 1);
    sgemm_kernel<false><<<gCP, 256>>>(cat, Wc, bc, nullptr, mha, NS, E_DIM, HE,
                                      E_DIM, E_DIM, 0, 0, 0, 0, 0, 0);

    // 8) y2 = LN2(mha + x)
    ln_kernel<<<NS, 256>>>(mha, x, g2, b2, y2);

    // 9) fc + GELU
    dim3 gFC(FF / 128, NS / 128, 1);
    sgemm_kernel<false><<<gFC, 256>>>(y2, Wfc, bfc, nullptr, hb, NS, FF, E_DIM,
                                      FF, FF, 0, 0, 0, 0, 1, 0);

    // 10) proj + residual -> out
    dim3 gPJ(E_DIM / 128, NS / 128, 1);
    sgemm_kernel<false><<<gPJ, 256>>>(hb, Wp, bp, y2, out, NS, E_DIM, FF,
                                      E_DIM, E_DIM, 0, 0, 0, 0, 2, 0);
}